// round 1
// baseline (speedup 1.0000x reference)
#include <cuda_runtime.h>
#include <math.h>

#define NN 50000
#define EE 800000
#define FH 128
#define CC 47
#define LL 3
#define BN_EPS 1e-5f

// -------- scratch (static __device__ globals: allocation-free) --------
__device__ float g_agg[NN * FH];
__device__ float g_z[NN * FH];
__device__ float g_h[NN * FH];
__device__ int g_deg[NN];
__device__ int g_rs[NN + 1];
__device__ int g_cur[NN];
__device__ int g_csr[EE];

// -------- CSR build --------
__global__ void k_zero_deg() {
    int i = blockIdx.x * blockDim.x + threadIdx.x;
    if (i < NN) g_deg[i] = 0;
}

__global__ void k_hist(const int* __restrict__ dst) {
    int i = blockIdx.x * blockDim.x + threadIdx.x;
    if (i < EE) atomicAdd(&g_deg[dst[i]], 1);
}

__global__ void __launch_bounds__(1024) k_scan() {
    __shared__ int s[1024];
    const int CH = (NN + 1023) / 1024;  // 49
    int tid = threadIdx.x;
    int start = tid * CH;
    int end = min(start + CH, NN);
    int loc = 0;
    for (int i = start; i < end; i++) loc += g_deg[i];
    s[tid] = loc;
    __syncthreads();
    for (int off = 1; off < 1024; off <<= 1) {
        int v = (tid >= off) ? s[tid - off] : 0;
        __syncthreads();
        s[tid] += v;
        __syncthreads();
    }
    int run = (tid == 0) ? 0 : s[tid - 1];
    for (int i = start; i < end; i++) {
        g_rs[i] = run;
        g_cur[i] = run;
        run += g_deg[i];
    }
    if (tid == 1023) g_rs[NN] = run;
}

__global__ void k_fill(const int* __restrict__ src, const int* __restrict__ dst) {
    int i = blockIdx.x * blockDim.x + threadIdx.x;
    if (i < EE) {
        int p = atomicAdd(&g_cur[dst[i]], 1);
        g_csr[p] = src[i];
    }
}

// -------- gather: agg[n] = h[n] + sum_{j in N(n)} h[j]  (warp per node) --------
__global__ void k_gather(const float* __restrict__ h, float* __restrict__ agg) {
    int gw = (blockIdx.x * blockDim.x + threadIdx.x) >> 5;
    int lane = threadIdx.x & 31;
    if (gw >= NN) return;
    const float4* h4 = (const float4*)h;
    float4 acc = h4[gw * 32 + lane];
    int beg = g_rs[gw], end = g_rs[gw + 1];
    for (int e = beg; e < end; e++) {
        int sidx = g_csr[e];
        float4 v = h4[sidx * 32 + lane];
        acc.x += v.x; acc.y += v.y; acc.z += v.z; acc.w += v.w;
    }
    ((float4*)agg)[gw * 32 + lane] = acc;
}

// -------- GEMM: out = relu(epilogue(A[M,128] @ W[128,128]))  --------
// HAS_BN: epilogue = ((acc + bias) - mean)*rsqrt(var+eps)*gamma + beta
// else:   epilogue = acc + bias
// Block: 64 rows x 128 cols, 256 threads, each thread 4x8 outputs.
template <bool HAS_BN>
__global__ void __launch_bounds__(256) k_gemm(
    const float* __restrict__ A, const float* __restrict__ W,
    const float* __restrict__ bias,
    const float* __restrict__ gamma, const float* __restrict__ beta,
    const float* __restrict__ mean, const float* __restrict__ var,
    float* __restrict__ out, int M)
{
    extern __shared__ float sm[];
    float(*Ws)[128] = (float(*)[128])sm;                 // 128x128  (k-major)
    float(*As)[68] = (float(*)[68])(sm + 128 * 128);     // 128x68   (k-major, padded)

    int tid = threadIdx.x;
    int row0 = blockIdx.x * 64;

    // load W (k-major already: W[k][n])
    {
        const float4* W4 = (const float4*)W;
        float4* Ws4 = (float4*)Ws;
#pragma unroll 4
        for (int i = tid; i < 128 * 128 / 4; i += 256) Ws4[i] = W4[i];
    }
    // load A tile transposed into As[k][m]
    for (int i = tid; i < 64 * 32; i += 256) {
        int r = i >> 5;
        int k4 = (i & 31) << 2;
        int row = row0 + r;
        float4 v = make_float4(0.f, 0.f, 0.f, 0.f);
        if (row < M) v = ((const float4*)(A + (long)row * 128))[i & 31];
        As[k4 + 0][r] = v.x;
        As[k4 + 1][r] = v.y;
        As[k4 + 2][r] = v.z;
        As[k4 + 3][r] = v.w;
    }
    __syncthreads();

    int tr = tid & 15;   // row group: rows tr*4..+3
    int tc = tid >> 4;   // col group: cols tc*8..+7

    float acc[4][8];
#pragma unroll
    for (int i = 0; i < 4; i++)
#pragma unroll
        for (int j = 0; j < 8; j++) acc[i][j] = 0.f;

#pragma unroll 8
    for (int k = 0; k < 128; k++) {
        float4 a = *(const float4*)&As[k][tr * 4];
        float4 w0 = *(const float4*)&Ws[k][tc * 8];
        float4 w1 = *(const float4*)&Ws[k][tc * 8 + 4];
        float av[4] = {a.x, a.y, a.z, a.w};
        float wv[8] = {w0.x, w0.y, w0.z, w0.w, w1.x, w1.y, w1.z, w1.w};
#pragma unroll
        for (int i = 0; i < 4; i++)
#pragma unroll
            for (int j = 0; j < 8; j++) acc[i][j] = fmaf(av[i], wv[j], acc[i][j]);
    }

    // epilogue
    float sc[8], sh[8];
#pragma unroll
    for (int j = 0; j < 8; j++) {
        int c = tc * 8 + j;
        if (HAS_BN) {
            float s = gamma[c] * rsqrtf(var[c] + BN_EPS);
            sc[j] = s;
            sh[j] = (bias[c] - mean[c]) * s + beta[c];
        } else {
            sc[j] = 1.f;
            sh[j] = bias[c];
        }
    }
#pragma unroll
    for (int i = 0; i < 4; i++) {
        int row = row0 + tr * 4 + i;
        if (row < M) {
            float4 o0, o1;
            o0.x = fmaxf(fmaf(acc[i][0], sc[0], sh[0]), 0.f);
            o0.y = fmaxf(fmaf(acc[i][1], sc[1], sh[1]), 0.f);
            o0.z = fmaxf(fmaf(acc[i][2], sc[2], sh[2]), 0.f);
            o0.w = fmaxf(fmaf(acc[i][3], sc[3], sh[3]), 0.f);
            o1.x = fmaxf(fmaf(acc[i][4], sc[4], sh[4]), 0.f);
            o1.y = fmaxf(fmaf(acc[i][5], sc[5], sh[5]), 0.f);
            o1.z = fmaxf(fmaf(acc[i][6], sc[6], sh[6]), 0.f);
            o1.w = fmaxf(fmaf(acc[i][7], sc[7], sh[7]), 0.f);
            float* op = out + (long)row * 128 + tc * 8;
            ((float4*)op)[0] = o0;
            ((float4*)(op + 4))[0] = o1;
        }
    }
}

// -------- head: logits = H @ lw2 + lb2 ; out = log_softmax(logits) --------
// Block: 32 nodes, 256 threads.
__global__ void __launch_bounds__(256) k_head(
    const float* __restrict__ Hm, const float* __restrict__ lw2,
    const float* __restrict__ lb2, float* __restrict__ out, int M)
{
    __shared__ float Hs[32][129];
    __shared__ float Ws[128][48];
    __shared__ float Ls[32][48];
    __shared__ float lb[48];

    int tid = threadIdx.x;
    int node0 = blockIdx.x * 32;

    for (int i = tid; i < 128 * 48; i += 256) {
        int k = i / 48, c = i % 48;
        Ws[k][c] = (c < CC) ? lw2[k * CC + c] : 0.f;
    }
    if (tid < 48) lb[tid] = (tid < CC) ? lb2[tid] : 0.f;
    for (int i = tid; i < 32 * 128; i += 256) {
        int r = i >> 7, k = i & 127;
        int row = node0 + r;
        Hs[r][k] = (row < M) ? Hm[(long)row * 128 + k] : 0.f;
    }
    __syncthreads();

    // phase A: logits
    int nd = tid >> 3, cg = tid & 7;  // node 0..31, 6 cols each of 48
    float acc[6];
#pragma unroll
    for (int j = 0; j < 6; j++) acc[j] = lb[cg * 6 + j];
#pragma unroll 4
    for (int k = 0; k < 128; k++) {
        float hv = Hs[nd][k];
#pragma unroll
        for (int j = 0; j < 6; j++) acc[j] = fmaf(hv, Ws[k][cg * 6 + j], acc[j]);
    }
#pragma unroll
    for (int j = 0; j < 6; j++) Ls[nd][cg * 6 + j] = acc[j];
    __syncthreads();

    // phase B: log_softmax, warp handles 4 nodes
    int wid = tid >> 5, lane = tid & 31;
    for (int t = 0; t < 4; t++) {
        int n = wid * 4 + t;
        int row = node0 + n;
        float v0 = (lane < CC) ? Ls[n][lane] : -INFINITY;
        float v1 = (lane + 32 < CC) ? Ls[n][lane + 32] : -INFINITY;
        float m = fmaxf(v0, v1);
#pragma unroll
        for (int off = 16; off > 0; off >>= 1)
            m = fmaxf(m, __shfl_xor_sync(0xffffffffu, m, off));
        float s = expf(v0 - m) + ((lane + 32 < CC) ? expf(v1 - m) : 0.f);
#pragma unroll
        for (int off = 16; off > 0; off >>= 1)
            s += __shfl_xor_sync(0xffffffffu, s, off);
        float lse = m + logf(s);
        if (row < M) {
            if (lane < CC) out[(long)row * CC + lane] = v0 - lse;
            if (lane + 32 < CC) out[(long)row * CC + lane + 32] = v1 - lse;
        }
    }
}

// -------- launch --------
extern "C" void kernel_launch(void* const* d_in, const int* in_sizes, int n_in,
                              void* d_out, int out_size) {
    const float* x = (const float*)d_in[0];
    const int* ei = (const int*)d_in[1];
    const float* W1 = (const float*)d_in[2];
    const float* b1 = (const float*)d_in[3];
    const float* gamma = (const float*)d_in[4];
    const float* beta = (const float*)d_in[5];
    const float* bnm = (const float*)d_in[6];
    const float* bnv = (const float*)d_in[7];
    const float* W2 = (const float*)d_in[8];
    const float* b2 = (const float*)d_in[9];
    const float* lw1 = (const float*)d_in[10];
    const float* lb1 = (const float*)d_in[11];
    const float* lw2 = (const float*)d_in[12];
    const float* lb2 = (const float*)d_in[13];
    float* out = (float*)d_out;

    const int* src = ei;
    const int* dst = ei + EE;

    float *agg, *z, *h;
    cudaGetSymbolAddress((void**)&agg, g_agg);
    cudaGetSymbolAddress((void**)&z, g_z);
    cudaGetSymbolAddress((void**)&h, g_h);

    const int GEMM_SMEM = (128 * 128 + 128 * 68) * (int)sizeof(float);  // 100352 B
    cudaFuncSetAttribute(k_gemm<true>, cudaFuncAttributeMaxDynamicSharedMemorySize, GEMM_SMEM);
    cudaFuncSetAttribute(k_gemm<false>, cudaFuncAttributeMaxDynamicSharedMemorySize, GEMM_SMEM);

    // CSR build (once per call, reused across the 3 layers)
    k_zero_deg<<<(NN + 255) / 256, 256>>>();
    k_hist<<<(EE + 255) / 256, 256>>>(dst);
    k_scan<<<1, 1024>>>();
    k_fill<<<(EE + 255) / 256, 256>>>(src, dst);

    const int GEMM_GRID = (NN + 63) / 64;
    const float* hin = x;
    for (int i = 0; i < LL; i++) {
        k_gather<<<(NN * 32 + 255) / 256, 256>>>(hin, agg);
        k_gemm<true><<<GEMM_GRID, 256, GEMM_SMEM>>>(
            agg, W1 + i * FH * FH, b1 + i * FH,
            gamma + i * FH, beta + i * FH, bnm + i * FH, bnv + i * FH,
            z, NN);
        k_gemm<false><<<GEMM_GRID, 256, GEMM_SMEM>>>(
            z, W2 + i * FH * FH, b2 + i * FH,
            nullptr, nullptr, nullptr, nullptr,
            h, NN);
        hin = h;
    }
    // head linear 1 (relu)
    k_gemm<false><<<GEMM_GRID, 256, GEMM_SMEM>>>(
        h, lw1, lb1, nullptr, nullptr, nullptr, nullptr, z, NN);
    // head linear 2 + log_softmax
    k_head<<<(NN + 31) / 32, 256>>>(z, lw2, lb2, out, NN);
}

// round 4
// speedup vs baseline: 1.6940x; 1.6940x over previous
#include <cuda_runtime.h>
#include <math.h>
#include <stdint.h>

#define NN 50000
#define EE 800000
#define FH 128
#define CC 47
#define LL 3
#define BN_EPS 1e-5f

// -------- scratch (static __device__ globals: allocation-free) --------
__device__ float g_agg[NN * FH];
__device__ float g_z[NN * FH];
__device__ float g_h[NN * FH];
__device__ int g_deg[NN];
__device__ int g_rs[NN + 1];
__device__ int g_cur[NN];
__device__ int g_csr[EE];

// ======================= CSR build =======================
__global__ void k_zero_deg() {
    int i = blockIdx.x * blockDim.x + threadIdx.x;
    if (i < NN) g_deg[i] = 0;
}
__global__ void k_hist(const int* __restrict__ dst) {
    int i = blockIdx.x * blockDim.x + threadIdx.x;
    if (i < EE) atomicAdd(&g_deg[dst[i]], 1);
}
__global__ void __launch_bounds__(1024) k_scan() {
    __shared__ int s[1024];
    const int CH = (NN + 1023) / 1024;
    int tid = threadIdx.x;
    int start = tid * CH;
    int end = min(start + CH, NN);
    int loc = 0;
    for (int i = start; i < end; i++) loc += g_deg[i];
    s[tid] = loc;
    __syncthreads();
    for (int off = 1; off < 1024; off <<= 1) {
        int v = (tid >= off) ? s[tid - off] : 0;
        __syncthreads();
        s[tid] += v;
        __syncthreads();
    }
    int run = (tid == 0) ? 0 : s[tid - 1];
    for (int i = start; i < end; i++) {
        g_rs[i] = run;
        g_cur[i] = run;
        run += g_deg[i];
    }
    if (tid == 1023) g_rs[NN] = run;
}
__global__ void k_fill(const int* __restrict__ src, const int* __restrict__ dst) {
    int i = blockIdx.x * blockDim.x + threadIdx.x;
    if (i < EE) {
        int p = atomicAdd(&g_cur[dst[i]], 1);
        g_csr[p] = src[i];
    }
}

// ======================= gather (warp per node) =======================
__global__ void k_gather(const float* __restrict__ h, float* __restrict__ agg) {
    int gw = (blockIdx.x * blockDim.x + threadIdx.x) >> 5;
    int lane = threadIdx.x & 31;
    if (gw >= NN) return;
    const float4* h4 = (const float4*)h;
    float4 acc = h4[gw * 32 + lane];
    int beg = g_rs[gw], end = g_rs[gw + 1];
    for (int e = beg; e < end; e++) {
        int sidx = g_csr[e];
        float4 v = h4[sidx * 32 + lane];
        acc.x += v.x; acc.y += v.y; acc.z += v.z; acc.w += v.w;
    }
    ((float4*)agg)[gw * 32 + lane] = acc;
}

// ======================= tf32 mma.sync GEMM =======================
// out = relu(epi(A[M,128] @ W[128,128])), W given [k][n] (col-major B for mma)
// Block: 256 thr = 8 warps, tile 128x128. Warp = 32 rows x 64 cols.
__device__ __forceinline__ uint32_t f2tf(float f) {
    uint32_t r;
    asm("cvt.rna.tf32.f32 %0, %1;" : "=r"(r) : "f"(f));
    return r;
}
__device__ __forceinline__ void mma8(float c[4], const uint32_t a[4], uint32_t b0, uint32_t b1) {
    asm volatile(
        "mma.sync.aligned.m16n8k8.row.col.f32.tf32.tf32.f32 "
        "{%0,%1,%2,%3}, {%4,%5,%6,%7}, {%8,%9}, {%0,%1,%2,%3};"
        : "+f"(c[0]), "+f"(c[1]), "+f"(c[2]), "+f"(c[3])
        : "r"(a[0]), "r"(a[1]), "r"(a[2]), "r"(a[3]), "r"(b0), "r"(b1));
}

#define TSTRIDE 132
// dyn smem: As[128][132] u32, Ws[128][132] u32, scs[128] f32, shs[128] f32
#define SM_AS 0
#define SM_WS (128 * TSTRIDE)
#define SM_SC (2 * 128 * TSTRIDE)
#define SM_SH (SM_SC + 128)
#define SM_WORDS (SM_SH + 128)

template <bool HAS_BN>
__global__ void __launch_bounds__(256) k_mgemm(
    const float* __restrict__ A, const float* __restrict__ W,
    const float* __restrict__ bias,
    const float* __restrict__ gamma, const float* __restrict__ beta,
    const float* __restrict__ mean, const float* __restrict__ var,
    float* __restrict__ out, int M)
{
    extern __shared__ uint32_t sm[];
    uint32_t* As = sm + SM_AS;
    uint32_t* Ws = sm + SM_WS;
    float* scs = (float*)(sm + SM_SC);
    float* shs = (float*)(sm + SM_SH);

    int tid = threadIdx.x;
    int row0 = blockIdx.x * 128;

    if (tid < 128) {
        if (HAS_BN) {
            float s = gamma[tid] * rsqrtf(var[tid] + BN_EPS);
            scs[tid] = s;
            shs[tid] = (bias[tid] - mean[tid]) * s + beta[tid];
        } else {
            scs[tid] = 1.f;
            shs[tid] = bias[tid];
        }
    }

    // stage A and W tiles (tf32-rounded), 128 rows x 32 float4 chunks each
#pragma unroll
    for (int it = 0; it < 16; it++) {
        int c = tid + it * 256;
        int row = c >> 5, kc = (c & 31) << 2;
        int grow = row0 + row;
        float4 va = make_float4(0.f, 0.f, 0.f, 0.f);
        if (grow < M) va = *(const float4*)(A + (long)grow * 128 + kc);
        uint32_t* pa = As + row * TSTRIDE + kc;
        pa[0] = f2tf(va.x); pa[1] = f2tf(va.y); pa[2] = f2tf(va.z); pa[3] = f2tf(va.w);
        float4 vw = *(const float4*)(W + (long)row * 128 + kc);
        uint32_t* pw = Ws + row * TSTRIDE + kc;
        pw[0] = f2tf(vw.x); pw[1] = f2tf(vw.y); pw[2] = f2tf(vw.z); pw[3] = f2tf(vw.w);
    }
    __syncthreads();

    int wid = tid >> 5, lane = tid & 31;
    int wr = (wid & 3) * 32;   // warp row band
    int wc = (wid >> 2) * 64;  // warp col band
    int g = lane >> 2, t = lane & 3;

    float acc[2][8][4];
#pragma unroll
    for (int i = 0; i < 2; i++)
#pragma unroll
        for (int j = 0; j < 8; j++)
#pragma unroll
            for (int q = 0; q < 4; q++) acc[i][j][q] = 0.f;

#pragma unroll 4
    for (int ks = 0; ks < 16; ks++) {
        int k0 = ks * 8;
        uint32_t af[2][4];
#pragma unroll
        for (int i = 0; i < 2; i++) {
            int m0 = wr + i * 16;
            af[i][0] = As[(m0 + g) * TSTRIDE + k0 + t];
            af[i][1] = As[(m0 + g + 8) * TSTRIDE + k0 + t];
            af[i][2] = As[(m0 + g) * TSTRIDE + k0 + t + 4];
            af[i][3] = As[(m0 + g + 8) * TSTRIDE + k0 + t + 4];
        }
#pragma unroll
        for (int j = 0; j < 8; j++) {
            int n0 = wc + j * 8;
            uint32_t b0 = Ws[(k0 + t) * TSTRIDE + n0 + g];
            uint32_t b1 = Ws[(k0 + t + 4) * TSTRIDE + n0 + g];
            mma8(acc[0][j], af[0], b0, b1);
            mma8(acc[1][j], af[1], b0, b1);
        }
    }

    // epilogue: thread owns rows {wr+i*16+g, +8}, cols {wc+j*8+2t, +1}
#pragma unroll
    for (int i = 0; i < 2; i++) {
        int r0 = row0 + wr + i * 16 + g;
        int r1 = r0 + 8;
#pragma unroll
        for (int j = 0; j < 8; j++) {
            int c0 = wc + j * 8 + 2 * t;
            float s0 = scs[c0], s1 = scs[c0 + 1];
            float h0 = shs[c0], h1 = shs[c0 + 1];
            if (r0 < M) {
                float2 o;
                o.x = fmaxf(fmaf(acc[i][j][0], s0, h0), 0.f);
                o.y = fmaxf(fmaf(acc[i][j][1], s1, h1), 0.f);
                *(float2*)(out + (long)r0 * 128 + c0) = o;
            }
            if (r1 < M) {
                float2 o;
                o.x = fmaxf(fmaf(acc[i][j][2], s0, h0), 0.f);
                o.y = fmaxf(fmaf(acc[i][j][3], s1, h1), 0.f);
                *(float2*)(out + (long)r1 * 128 + c0) = o;
            }
        }
    }
}

// ======================= head: logits + log_softmax =======================
__global__ void __launch_bounds__(256) k_head(
    const float* __restrict__ Hm, const float* __restrict__ lw2,
    const float* __restrict__ lb2, float* __restrict__ out, int M)
{
    __shared__ float Hs[32][129];
    __shared__ float Ws[128][48];
    __shared__ float Ls[32][48];
    __shared__ float lb[48];

    int tid = threadIdx.x;
    int node0 = blockIdx.x * 32;

    for (int i = tid; i < 128 * 48; i += 256) {
        int k = i / 48, c = i % 48;
        Ws[k][c] = (c < CC) ? lw2[k * CC + c] : 0.f;
    }
    if (tid < 48) lb[tid] = (tid < CC) ? lb2[tid] : 0.f;
    for (int i = tid; i < 32 * 128; i += 256) {
        int r = i >> 7, k = i & 127;
        int row = node0 + r;
        Hs[r][k] = (row < M) ? Hm[(long)row * 128 + k] : 0.f;
    }
    __syncthreads();

    int nd = tid >> 3, cg = tid & 7;
    float acc[6];
#pragma unroll
    for (int j = 0; j < 6; j++) acc[j] = lb[cg * 6 + j];
#pragma unroll 4
    for (int k = 0; k < 128; k++) {
        float hv = Hs[nd][k];
#pragma unroll
        for (int j = 0; j < 6; j++) acc[j] = fmaf(hv, Ws[k][cg * 6 + j], acc[j]);
    }
#pragma unroll
    for (int j = 0; j < 6; j++) Ls[nd][cg * 6 + j] = acc[j];
    __syncthreads();

    int wid = tid >> 5, lane = tid & 31;
    for (int t = 0; t < 4; t++) {
        int n = wid * 4 + t;
        int row = node0 + n;
        float v0 = (lane < CC) ? Ls[n][lane] : -INFINITY;
        float v1 = (lane + 32 < CC) ? Ls[n][lane + 32] : -INFINITY;
        float m = fmaxf(v0, v1);
#pragma unroll
        for (int off = 16; off > 0; off >>= 1)
            m = fmaxf(m, __shfl_xor_sync(0xffffffffu, m, off));
        float s = expf(v0 - m) + ((lane + 32 < CC) ? expf(v1 - m) : 0.f);
#pragma unroll
        for (int off = 16; off > 0; off >>= 1)
            s += __shfl_xor_sync(0xffffffffu, s, off);
        float lse = m + logf(s);
        if (row < M) {
            if (lane < CC) out[(long)row * CC + lane] = v0 - lse;
            if (lane + 32 < CC) out[(long)row * CC + lane + 32] = v1 - lse;
        }
    }
}

// ======================= launch =======================
extern "C" void kernel_launch(void* const* d_in, const int* in_sizes, int n_in,
                              void* d_out, int out_size) {
    const float* x = (const float*)d_in[0];
    const int* ei = (const int*)d_in[1];
    const float* W1 = (const float*)d_in[2];
    const float* b1 = (const float*)d_in[3];
    const float* gamma = (const float*)d_in[4];
    const float* beta = (const float*)d_in[5];
    const float* bnm = (const float*)d_in[6];
    const float* bnv = (const float*)d_in[7];
    const float* W2 = (const float*)d_in[8];
    const float* b2 = (const float*)d_in[9];
    const float* lw1 = (const float*)d_in[10];
    const float* lb1 = (const float*)d_in[11];
    const float* lw2 = (const float*)d_in[12];
    const float* lb2 = (const float*)d_in[13];
    float* out = (float*)d_out;

    const int* src = ei;
    const int* dst = ei + EE;

    float *agg, *z, *h;
    cudaGetSymbolAddress((void**)&agg, g_agg);
    cudaGetSymbolAddress((void**)&z, g_z);
    cudaGetSymbolAddress((void**)&h, g_h);

    const int GEMM_SMEM = SM_WORDS * 4;  // ~136 KB
    cudaFuncSetAttribute(k_mgemm<true>, cudaFuncAttributeMaxDynamicSharedMemorySize, GEMM_SMEM);
    cudaFuncSetAttribute(k_mgemm<false>, cudaFuncAttributeMaxDynamicSharedMemorySize, GEMM_SMEM);

    // CSR build (reused across layers)
    k_zero_deg<<<(NN + 255) / 256, 256>>>();
    k_hist<<<(EE + 255) / 256, 256>>>(dst);
    k_scan<<<1, 1024>>>();
    k_fill<<<(EE + 255) / 256, 256>>>(src, dst);

    const int G = (NN + 127) / 128;  // 391
    const float* hin = x;
    for (int i = 0; i < LL; i++) {
        k_gather<<<(NN * 32 + 255) / 256, 256>>>(hin, agg);
        k_mgemm<true><<<G, 256, GEMM_SMEM>>>(
            agg, W1 + i * FH * FH, b1 + i * FH,
            gamma + i * FH, beta + i * FH, bnm + i * FH, bnv + i * FH,
            z, NN);
        k_mgemm<false><<<G, 256, GEMM_SMEM>>>(
            z, W2 + i * FH * FH, b2 + i * FH,
            nullptr, nullptr, nullptr, nullptr,
            h, NN);
        hin = h;
    }
    // head linear 1 (relu)
    k_mgemm<false><<<G, 256, GEMM_SMEM>>>(
        h, lw1, lb1, nullptr, nullptr, nullptr, nullptr, z, NN);
    // head linear 2 + log_softmax
    k_head<<<(NN + 31) / 32, 256>>>(z, lw2, lb2, out, NN);
}